// round 16
// baseline (speedup 1.0000x reference)
#include <cuda_runtime.h>

#define NQ 6
#define NL 3

typedef unsigned long long ull;

// ---- packed f32x2 helpers ----
__device__ __forceinline__ ull fma2(ull a, ull b, ull c) {
    ull d; asm("fma.rn.f32x2 %0,%1,%2,%3;" : "=l"(d) : "l"(a), "l"(b), "l"(c)); return d;
}
__device__ __forceinline__ ull mul2(ull a, ull b) {
    ull d; asm("mul.rn.f32x2 %0,%1,%2;" : "=l"(d) : "l"(a), "l"(b)); return d;
}
__device__ __forceinline__ ull add2(ull a, ull b) {
    ull d; asm("add.rn.f32x2 %0,%1,%2;" : "=l"(d) : "l"(a), "l"(b)); return d;
}
__device__ __forceinline__ ull pk(float lo, float hi) {
    ull d; asm("mov.b64 %0,{%1,%2};" : "=l"(d) : "f"(lo), "f"(hi)); return d;
}
__device__ __forceinline__ ull sp2(float x) { return pk(x, x); }
__device__ __forceinline__ float flo(ull v) { return __uint_as_float((unsigned)v); }
__device__ __forceinline__ float fhi(ull v) { return __uint_as_float((unsigned)(v >> 32)); }
__device__ __forceinline__ ull lsw(ull v) { return pk(fhi(v), flo(v)); }     // lane swap
__device__ __forceinline__ ull neg2(ull v) { return v ^ 0x8000000080000000ULL; }
__device__ __forceinline__ float tanh_fast(float x) {
    float y; asm("tanh.approx.f32 %0, %1;" : "=f"(y) : "f"(x)); return y;
}
// a - b on the fma pipe (1 op)
__device__ __forceinline__ ull sub2f(ull a, ull b, ull MONE) { return fma2(MONE, b, a); }

// Gate on local wire w: coefficient packs built from the pre-splatted shared
// layout P (12 ull: 0..7 = splat(m00x,m00y,m01x,m01y,m10x,m10y,m11x,m11y),
// 8..11 = splat(-m00y,-m01y,-m10y,-m11y)). Row offsets (ra,na,rb,nb) select
// which M row feeds G's row 0/1 — (0,8,4,10) normal; p-swapped for w1+C01fold.
template <int S>
__device__ __forceinline__ void gate_local_c(ull* RE, ull* IM, const ull* P,
                                             int ra, int na, int rb, int nb,
                                             ull csp, ull snp, ull nsnp) {
    ull x00 = fma2(csp, P[ra + 0], mul2(snp, P[ra + 2]));
    ull y00 = fma2(csp, P[ra + 1], mul2(snp, P[ra + 3]));
    ull ny00 = fma2(csp, P[na + 0], mul2(snp, P[na + 1]));
    ull x01 = fma2(csp, P[ra + 2], mul2(nsnp, P[ra + 0]));
    ull y01 = fma2(csp, P[ra + 3], mul2(nsnp, P[ra + 1]));
    ull ny01 = fma2(snp, P[ra + 1], mul2(csp, P[na + 1]));
    ull x10 = fma2(csp, P[rb + 0], mul2(snp, P[rb + 2]));
    ull y10 = fma2(csp, P[rb + 1], mul2(snp, P[rb + 3]));
    ull ny10 = fma2(csp, P[nb + 0], mul2(snp, P[nb + 1]));
    ull x11 = fma2(csp, P[rb + 2], mul2(nsnp, P[rb + 0]));
    ull y11 = fma2(csp, P[rb + 3], mul2(nsnp, P[rb + 1]));
    ull ny11 = fma2(snp, P[rb + 1], mul2(csp, P[nb + 1]));
#pragma unroll
    for (int t = 0; t < 8; t++) {
        int K0 = ((t & ~(S - 1)) << 1) | (t & (S - 1));
        int K1 = K0 + S;
        ull r0 = RE[K0], i0 = IM[K0], r1 = RE[K1], i1 = IM[K1];
        RE[K0] = fma2(x00, r0, fma2(ny00, i0, fma2(x01, r1, mul2(ny01, i1))));
        IM[K0] = fma2(x00, i0, fma2(y00, r0, fma2(x01, i1, mul2(y01, r1))));
        RE[K1] = fma2(x10, r0, fma2(ny10, i0, fma2(x11, r1, mul2(ny11, i1))));
        IM[K1] = fma2(x10, i0, fma2(y10, r0, fma2(x11, i1, mul2(y11, r1))));
    }
}

// Wire-5 coefficient packs from the paired shared layout W (12 ull):
//  Px = c*W0+s*W1, Py = c*W2+s*W3, nPy = c*W4+s*W5,
//  Qx = c*W6+s*W7, Qy = c*W8+s*W9, nQy = c*W10+s*W11.
__device__ __forceinline__ void w5_coeffs(const ull* W, ull csp, ull snp,
                                          ull& Px, ull& Py, ull& nPy,
                                          ull& Qx, ull& Qy, ull& nQy) {
    Px = fma2(csp, W[0], mul2(snp, W[1]));
    Py = fma2(csp, W[2], mul2(snp, W[3]));
    nPy = fma2(csp, W[4], mul2(snp, W[5]));
    Qx = fma2(csp, W[6], mul2(snp, W[7]));
    Qy = fma2(csp, W[8], mul2(snp, W[9]));
    nQy = fma2(csp, W[10], mul2(snp, W[11]));
}

// Gate on wire 5 (lanes): out = P .* st + Q .* laneswap(st).
__device__ __forceinline__ void gate_w5_c(ull* RE, ull* IM, const ull* W,
                                          ull csp, ull snp) {
    ull Px, Py, nPy, Qx, Qy, nQy;
    w5_coeffs(W, csp, snp, Px, Py, nPy, Qx, Qy, nQy);
#pragma unroll
    for (int K = 0; K < 16; K++) {
        ull r = RE[K], i = IM[K];
        ull rs = lsw(r), is = lsw(i);
        RE[K] = fma2(Px, r, fma2(nPy, i, fma2(Qx, rs, mul2(nQy, is))));
        IM[K] = fma2(Px, i, fma2(Py, r, fma2(Qx, is, mul2(Qy, rs))));
    }
}

// Wire-5 gate with the ring's cnot(4,5) FOLDED (odd K gets post-lane-swap):
// odd-K coefficient packs are just lane-swapped versions of the even ones.
__device__ __forceinline__ void gate_w5_foldC45_c(ull* RE, ull* IM, const ull* W,
                                                  ull csp, ull snp) {
    ull Px, Py, nPy, Qx, Qy, nQy;
    w5_coeffs(W, csp, snp, Px, Py, nPy, Qx, Qy, nQy);
#pragma unroll
    for (int K = 0; K < 16; K += 2) {
        ull r = RE[K], i = IM[K];
        ull rs = lsw(r), is = lsw(i);
        RE[K] = fma2(Px, r, fma2(nPy, i, fma2(Qx, rs, mul2(nQy, is))));
        IM[K] = fma2(Px, i, fma2(Py, r, fma2(Qx, is, mul2(Qy, rs))));
    }
    ull oPx = lsw(Px), oPy = lsw(Py), onPy = lsw(nPy);
    ull oQx = lsw(Qx), oQy = lsw(Qy), onQy = lsw(nQy);
#pragma unroll
    for (int K = 1; K < 16; K += 2) {
        ull r = RE[K], i = IM[K];
        ull rs = lsw(r), is = lsw(i);
        RE[K] = fma2(oQx, r, fma2(onQy, i, fma2(oPx, rs, mul2(onPy, is))));
        IM[K] = fma2(oQx, i, fma2(oQy, r, fma2(oPx, is, mul2(oPy, rs))));
    }
}

// Gate on wire 0 fused with a PENDING cnot(5,0) from the preceding ring.
// Asymmetric coefficient packs absorb the lane merge; 2-deep SHFL pipeline.
__device__ __forceinline__ void gate_w0_fused(ull* RE, ull* IM, float2 Gd, float2 Go) {
    ull dx = pk(Gd.x, Go.x), ox = pk(Go.x, Gd.x);
    ull dy = pk(Gd.y, Go.y), oy = pk(Go.y, Gd.y);
    ull ndy = pk(-Gd.y, -Go.y), noy = pk(-Go.y, -Gd.y);
    ull pr = __shfl_xor_sync(0xffffffffu, RE[0], 1);
    ull pi = __shfl_xor_sync(0xffffffffu, IM[0], 1);
#pragma unroll
    for (int K = 0; K < 16; K++) {
        ull prn = 0, pin = 0;
        if (K < 15) {
            prn = __shfl_xor_sync(0xffffffffu, RE[K + 1], 1);
            pin = __shfl_xor_sync(0xffffffffu, IM[K + 1], 1);
        }
        ull r = RE[K], i = IM[K];
        RE[K] = fma2(dx, r, fma2(ndy, i, fma2(ox, pr, mul2(noy, pi))));
        IM[K] = fma2(dx, i, fma2(dy, r, fma2(ox, pi, mul2(oy, pr))));
        pr = prn; pi = pin;
    }
}

__device__ __forceinline__ void swp(ull& a, ull& b) { ull t = a; a = b; b = t; }

// Free pack-index renames: cnot(1,2)(2,3)(3,4).
__device__ __forceinline__ void cnot_free_swaps(ull* RE, ull* IM) {
    swp(RE[8], RE[12]); swp(IM[8], IM[12]);
    swp(RE[9], RE[13]); swp(IM[9], IM[13]);
    swp(RE[10], RE[14]); swp(IM[10], IM[14]);
    swp(RE[11], RE[15]); swp(IM[11], IM[15]);
    swp(RE[4], RE[6]);  swp(IM[4], IM[6]);
    swp(RE[5], RE[7]);  swp(IM[5], IM[7]);
    swp(RE[12], RE[14]); swp(IM[12], IM[14]);
    swp(RE[13], RE[15]); swp(IM[13], IM[15]);
    swp(RE[2], RE[3]);  swp(IM[2], IM[3]);
    swp(RE[6], RE[7]);  swp(IM[6], IM[7]);
    swp(RE[10], RE[11]); swp(IM[10], IM[11]);
    swp(RE[14], RE[15]); swp(IM[14], IM[15]);
}

// Ring0 tail: free swaps + explicit cnot(4,5) lane swap on odd packs.
__device__ __forceinline__ void cnot_ring_rest(ull* RE, ull* IM) {
    cnot_free_swaps(RE, IM);
#pragma unroll
    for (int K = 1; K < 16; K += 2) {
        RE[K] = lsw(RE[K]);
        IM[K] = lsw(IM[K]);
    }
}

__global__ __launch_bounds__(128, 4)
void qsim_kernel(const float* __restrict__ x, const float* __restrict__ w,
                 float* __restrict__ out, int B) {
    // Shared gate data:
    //  sM   : raw M entries (float2) — used by scalar paths (w0 rows, q=1, readout w1)
    //  sP   : per-gate splat layout (12 ull) for packed coefficient builds
    //  sW5  : paired layout for the two mid/final wire-5 gates
    //  sV5  : paired layout for layer-0's wire-5 first-column factor
    __shared__ __align__(16) float2 sM[NL * NQ * 4];
    __shared__ __align__(16) ull sP[18 * 12];
    __shared__ __align__(16) ull sW5[2 * 12];
    __shared__ __align__(16) ull sV5[6];
    {
        int g = threadIdx.x;
        if (g < NL * NQ) {
            float w0 = w[g * 3 + 0];
            float w1 = w[g * 3 + 1];
            float w2 = w[g * 3 + 2];
            float s1, c1, sp_, cp_, sm2, cm2;
            sincosf(0.5f * w1, &s1, &c1);
            sincosf(0.5f * (w0 + w2), &sp_, &cp_);
            sincosf(0.5f * (w0 - w2), &sm2, &cm2);
            float2 m0 = make_float2(c1 * cp_, -c1 * sp_);   // M00
            float2 m1 = make_float2(-s1 * cm2, -s1 * sm2);  // M01
            float2 m2 = make_float2(s1 * cm2, -s1 * sm2);   // M10
            float2 m3 = make_float2(c1 * cp_, c1 * sp_);    // M11
            sM[g * 4 + 0] = m0; sM[g * 4 + 1] = m1;
            sM[g * 4 + 2] = m2; sM[g * 4 + 3] = m3;
            float2* P = reinterpret_cast<float2*>(&sP[g * 12]);
            P[0] = make_float2(m0.x, m0.x);  P[1] = make_float2(m0.y, m0.y);
            P[2] = make_float2(m1.x, m1.x);  P[3] = make_float2(m1.y, m1.y);
            P[4] = make_float2(m2.x, m2.x);  P[5] = make_float2(m2.y, m2.y);
            P[6] = make_float2(m3.x, m3.x);  P[7] = make_float2(m3.y, m3.y);
            P[8] = make_float2(-m0.y, -m0.y);  P[9] = make_float2(-m1.y, -m1.y);
            P[10] = make_float2(-m2.y, -m2.y); P[11] = make_float2(-m3.y, -m3.y);
            if (g == 5) {
                float2* V = reinterpret_cast<float2*>(sV5);
                V[0] = make_float2(m0.x, m2.x);   V[1] = make_float2(m1.x, m3.x);
                V[2] = make_float2(m0.y, m2.y);   V[3] = make_float2(m1.y, m3.y);
                V[4] = make_float2(-m0.y, -m2.y); V[5] = make_float2(-m1.y, -m3.y);
            }
            if (g == 11 || g == 17) {
                float2* W = reinterpret_cast<float2*>(&sW5[(g == 11 ? 0 : 1) * 12]);
                W[0]  = make_float2(m0.x, m3.x);   W[1]  = make_float2(m1.x, -m2.x);
                W[2]  = make_float2(m0.y, m3.y);   W[3]  = make_float2(m1.y, -m2.y);
                W[4]  = make_float2(-m0.y, -m3.y); W[5]  = make_float2(-m1.y, m2.y);
                W[6]  = make_float2(m1.x, m2.x);   W[7]  = make_float2(-m0.x, m3.x);
                W[8]  = make_float2(m1.y, m2.y);   W[9]  = make_float2(-m0.y, m3.y);
                W[10] = make_float2(-m1.y, -m2.y); W[11] = make_float2(m0.y, -m3.y);
            }
        }
    }
    __syncthreads();

    int tid = blockIdx.x * blockDim.x + threadIdx.x;
    int b = tid >> 1;
    if (b >= B) return;
    int p = tid & 1;  // this thread's wire-0 (MSB) value

    // Vectorized x load, then angles.
    float cs[NQ], sn[NQ];
    {
        const float2* xx = reinterpret_cast<const float2*>(x + (size_t)b * NQ);
        float2 x01 = xx[0], x23 = xx[1], x45 = xx[2];
        float xv[NQ] = {x01.x, x01.y, x23.x, x23.y, x45.x, x45.y};
#pragma unroll
        for (int q = 0; q < NQ; q++) {
            float t = 1.5707963267948966f * tanh_fast(xv[q]);
            __sincosf(t, &sn[q], &cs[q]);
        }
    }

    // 32 local amps packed: RE[K] = (re_{2K}, re_{2K+1}), pack lane = wire5.
    // Pack-index bits k3..k0 = wires 1..4.
    ull RE[16], IM[16];

    // ---- Layer 0: product state |0..0> -> tensor of first gate columns.
    //      Ring0's cnot(0,1) folded into the wire-1 factor (v0<->v1 for p=1). ----
    {
        float2 a;  // wire-0 factor for this thread
        {
            float2 ma = p ? sM[2] : sM[0];
            float2 mb = p ? sM[3] : sM[1];
            a.x = fmaf(cs[0], ma.x, sn[0] * mb.x);
            a.y = fmaf(cs[0], ma.y, sn[0] * mb.y);
        }
        {
            ull c5 = sp2(cs[5]), s5 = sp2(sn[5]);
            ull V5X = fma2(c5, sV5[0], mul2(s5, sV5[1]));
            ull V5Y = fma2(c5, sV5[2], mul2(s5, sV5[3]));
            ull V5Yn = fma2(c5, sV5[4], mul2(s5, sV5[5]));
            ull ax = sp2(a.x), ay = sp2(a.y);
            RE[0] = fma2(ax, V5X, mul2(ay, V5Yn));
            IM[0] = fma2(ax, V5Y, mul2(ay, V5X));
        }
        // q=1 (scalar path; ring0's cnot(0,1) fold = v0<->v1 select for p=1)
        {
            float2 m00 = sM[4], m01 = sM[5], m10 = sM[6], m11 = sM[7];
            float2 v0 = make_float2(fmaf(cs[1], m00.x, sn[1] * m01.x),
                                    fmaf(cs[1], m00.y, sn[1] * m01.y));
            float2 v1 = make_float2(fmaf(cs[1], m10.x, sn[1] * m11.x),
                                    fmaf(cs[1], m10.y, sn[1] * m11.y));
            float2 t0 = v0, t1 = v1;
            v0 = p ? t1 : t0;
            v1 = p ? t0 : t1;
            ull x0 = sp2(v0.x), ny0 = sp2(-v0.y), y0 = sp2(v0.y);
            ull x1 = sp2(v1.x), ny1 = sp2(-v1.y), y1 = sp2(v1.y);
            ull r = RE[0], i = IM[0];
            RE[1] = fma2(x1, r, mul2(ny1, i));
            IM[1] = fma2(x1, i, mul2(y1, r));
            RE[0] = fma2(x0, r, mul2(ny0, i));
            IM[0] = fma2(x0, i, mul2(y0, r));
        }
        // q=2..4 (packed coefficient builds from sP)
#pragma unroll
        for (int q = 2; q <= 4; q++) {
            const ull* P = &sP[q * 12];
            ull csp = sp2(cs[q]), snp = sp2(sn[q]);
            ull x0 = fma2(csp, P[0], mul2(snp, P[2]));
            ull y0 = fma2(csp, P[1], mul2(snp, P[3]));
            ull ny0 = fma2(csp, P[8], mul2(snp, P[9]));
            ull x1 = fma2(csp, P[4], mul2(snp, P[6]));
            ull y1 = fma2(csp, P[5], mul2(snp, P[7]));
            ull ny1 = fma2(csp, P[10], mul2(snp, P[11]));
            int n = 1 << (q - 1);
#pragma unroll
            for (int k = 15; k >= 0; k--) {
                if (k < n) {
                    ull r = RE[k], i = IM[k];
                    RE[2 * k + 1] = fma2(x1, r, mul2(ny1, i));
                    IM[2 * k + 1] = fma2(x1, i, mul2(y1, r));
                    RE[2 * k]     = fma2(x0, r, mul2(ny0, i));
                    IM[2 * k]     = fma2(x0, i, mul2(y0, r));
                }
            }
        }
    }
    cnot_ring_rest(RE, IM);  // ring0: (1,2)(2,3)(3,4)(4,5); cnot(5,0) pending

    // ---- Layer 1: w0(C50 fused), w2..w4, w1(C01 fold via row offsets),
    //      free swaps, then w5 with cnot(4,5) FOLDED. Leaves cnot(5,0) pending. ----
    {
        const float2* mbase = &sM[1 * NQ * 4];
        {
            float2 ma = p ? mbase[2] : mbase[0];
            float2 mb = p ? mbase[3] : mbase[1];
            float c = cs[0], s = sn[0];
            float2 u = make_float2(fmaf(c, ma.x, s * mb.x), fmaf(c, ma.y, s * mb.y));
            float2 v = make_float2(fmaf(-s, ma.x, c * mb.x), fmaf(-s, ma.y, c * mb.y));
            float2 Gd = p ? v : u;
            float2 Go = p ? u : v;
            gate_w0_fused(RE, IM, Gd, Go);
        }
        {
            ull csp = sp2(cs[2]), snp = sp2(sn[2]), nsnp = neg2(snp);
            gate_local_c<4>(RE, IM, &sP[8 * 12], 0, 8, 4, 10, csp, snp, nsnp);
        }
        {
            ull csp = sp2(cs[3]), snp = sp2(sn[3]), nsnp = neg2(snp);
            gate_local_c<2>(RE, IM, &sP[9 * 12], 0, 8, 4, 10, csp, snp, nsnp);
        }
        {
            ull csp = sp2(cs[4]), snp = sp2(sn[4]), nsnp = neg2(snp);
            gate_local_c<1>(RE, IM, &sP[10 * 12], 0, 8, 4, 10, csp, snp, nsnp);
        }
        // w1 with cnot(0,1) folded: p==1 applies X·G = row swap, realized as
        // p-dependent row offsets into the same splat layout.
        {
            ull csp = sp2(cs[1]), snp = sp2(sn[1]), nsnp = neg2(snp);
            int ra = p * 4, rb = 4 - p * 4;
            int na = 8 + p * 2, nb = 10 - p * 2;
            gate_local_c<8>(RE, IM, &sP[7 * 12], ra, na, rb, nb, csp, snp, nsnp);
        }
        cnot_free_swaps(RE, IM);
        {
            ull csp = sp2(cs[5]), snp = sp2(sn[5]);
            gate_w5_foldC45_c(RE, IM, &sW5[0], csp, snp);
        }
    }

    // ---- Layer 2 (final): w0(C50 fused), w2..w4, w5. Final wire-1 gate is
    //      FUSED into the readout via unitarity; final ring folded into
    //      the readout sign permutation. ----
    const float2* mbase2 = &sM[2 * NQ * 4];
    {
        {
            float2 ma = p ? mbase2[2] : mbase2[0];
            float2 mb = p ? mbase2[3] : mbase2[1];
            float c = cs[0], s = sn[0];
            float2 u = make_float2(fmaf(c, ma.x, s * mb.x), fmaf(c, ma.y, s * mb.y));
            float2 v = make_float2(fmaf(-s, ma.x, c * mb.x), fmaf(-s, ma.y, c * mb.y));
            float2 Gd = p ? v : u;
            float2 Go = p ? u : v;
            gate_w0_fused(RE, IM, Gd, Go);
        }
        {
            ull csp = sp2(cs[2]), snp = sp2(sn[2]), nsnp = neg2(snp);
            gate_local_c<4>(RE, IM, &sP[14 * 12], 0, 8, 4, 10, csp, snp, nsnp);
        }
        {
            ull csp = sp2(cs[3]), snp = sp2(sn[3]), nsnp = neg2(snp);
            gate_local_c<2>(RE, IM, &sP[15 * 12], 0, 8, 4, 10, csp, snp, nsnp);
        }
        {
            ull csp = sp2(cs[4]), snp = sp2(sn[4]), nsnp = neg2(snp);
            gate_local_c<1>(RE, IM, &sP[16 * 12], 0, 8, 4, 10, csp, snp, nsnp);
        }
        {
            ull csp = sp2(cs[5]), snp = sp2(sn[5]);
            gate_w5_c(RE, IM, &sW5[12], csp, snp);
        }
        // (no w1 gate — fused into DP below)
    }

    // ---- Readout with final-w1-gate fusion + final-ring fold.
    //   |u|^2-|v|^2 = alpha*(|a|^2-|b|^2)
    //               + 4*[Re(G00 cG01)*Re(a cb) - Im(G00 cG01)*Im(a cb)]
    //   alpha = |G00|^2-|G10|^2. Then 3-level Walsh on DP (wires 2,3,4). ----
    const ull MONE = sp2(-1.0f);
    ull tA, tBr, tBi;
    {
        const float4* m4 = reinterpret_cast<const float4*>(mbase2 + 4);
        float4 ah = m4[0], bh = m4[1];
        float c = cs[1], s = sn[1];
        float2 g00 = make_float2(fmaf(c, ah.x, s * ah.z), fmaf(c, ah.y, s * ah.w));
        float2 g01 = make_float2(fmaf(-s, ah.x, c * ah.z), fmaf(-s, ah.y, c * ah.w));
        float2 g10 = make_float2(fmaf(c, bh.x, s * bh.z), fmaf(c, bh.y, s * bh.w));
        float alpha = fmaf(g00.x, g00.x, g00.y * g00.y)
                    - fmaf(g10.x, g10.x, g10.y * g10.y);
        float betr = 4.0f * fmaf(g00.x, g01.x, g00.y * g01.y);   // 4*Re(G00 cG01)
        float beti = 4.0f * fmaf(g00.x, g01.y, -g00.y * g01.x);  // -4*Im(G00 cG01)
        tA = sp2(alpha); tBr = sp2(betr); tBi = sp2(beti);
    }
    ull DP[8];
#pragma unroll
    for (int K = 0; K < 8; K++) {
        ull ar = RE[K], ai = IM[K], br = RE[K + 8], bi = IM[K + 8];
        ull na = fma2(ar, ar, mul2(ai, ai));                    // |a|^2
        ull nb = fma2(br, br, mul2(bi, bi));                    // |b|^2
        ull Z  = sub2f(na, nb, MONE);
        ull Rc = fma2(ai, bi, mul2(ar, br));                    // Re(a conj b)
        ull Ic = sub2f(mul2(ai, br), mul2(ar, bi), MONE);       // Im(a conj b)
        DP[K] = fma2(tA, Z, fma2(tBr, Rc, mul2(tBi, Ic)));
    }
    // Walsh butterfly on DP: bit0 first, then bit1, then bit2.
    ull A0 = add2(DP[0], DP[1]), A1 = add2(DP[2], DP[3]);
    ull A2 = add2(DP[4], DP[5]), A3 = add2(DP[6], DP[7]);
    ull D0 = sub2f(DP[0], DP[1], MONE), D1 = sub2f(DP[2], DP[3], MONE);
    ull D2 = sub2f(DP[4], DP[5], MONE), D3 = sub2f(DP[6], DP[7], MONE);
    ull S0 = add2(A0, A1), S1 = add2(A2, A3);
    ull U0 = sub2f(A0, A1, MONE), U1 = sub2f(A2, A3, MONE);
    ull V0 = sub2f(D0, D1, MONE), V1 = sub2f(D2, D3, MONE);
    ull E1v = add2(S0, S1);            // sign: wire1 only (in DP)
    ull E2v = sub2f(S0, S1, MONE);     // + wire2
    ull E3v = sub2f(U0, U1, MONE);     // + wires2,3
    ull E4v = sub2f(V0, V1, MONE);     // + wires2,3,4

    float sg = p ? -1.0f : 1.0f;
    float e1 = sg * (flo(E1v) + fhi(E1v));
    float e2 = sg * (flo(E2v) + fhi(E2v));
    float e3 = sg * (flo(E3v) + fhi(E3v));
    float e4 = sg * (flo(E4v) + fhi(E4v));
    float g5 = flo(E4v) - fhi(E4v);
    float e5 = sg * g5;
    float e0 = g5;

    e0 += __shfl_xor_sync(0xffffffffu, e0, 1);
    e1 += __shfl_xor_sync(0xffffffffu, e1, 1);
    e2 += __shfl_xor_sync(0xffffffffu, e2, 1);
    e3 += __shfl_xor_sync(0xffffffffu, e3, 1);
    e4 += __shfl_xor_sync(0xffffffffu, e4, 1);
    e5 += __shfl_xor_sync(0xffffffffu, e5, 1);

    float* ob = out + (size_t)b * NQ;
    if (p == 0) {
        *reinterpret_cast<float2*>(ob) = make_float2(e0, e1);
        ob[2] = e2;
    } else {
        ob[3] = e3;
        *reinterpret_cast<float2*>(ob + 4) = make_float2(e4, e5);
    }
}

extern "C" void kernel_launch(void* const* d_in, const int* in_sizes, int n_in,
                              void* d_out, int out_size) {
    const float* x = (const float*)d_in[0];
    const float* w = (const float*)d_in[1];
    float* out = (float*)d_out;
    int B = in_sizes[0] / NQ;

    const int threads = 128;
    long long total = 2LL * B;
    int blocks = (int)((total + threads - 1) / threads);
    qsim_kernel<<<blocks, threads>>>(x, w, out, B);
}

// round 17
// speedup vs baseline: 1.1540x; 1.1540x over previous
#include <cuda_runtime.h>

#define NQ 6
#define NL 3

typedef unsigned long long ull;

// ---- packed f32x2 helpers ----
__device__ __forceinline__ ull fma2(ull a, ull b, ull c) {
    ull d; asm("fma.rn.f32x2 %0,%1,%2,%3;" : "=l"(d) : "l"(a), "l"(b), "l"(c)); return d;
}
__device__ __forceinline__ ull mul2(ull a, ull b) {
    ull d; asm("mul.rn.f32x2 %0,%1,%2;" : "=l"(d) : "l"(a), "l"(b)); return d;
}
__device__ __forceinline__ ull add2(ull a, ull b) {
    ull d; asm("add.rn.f32x2 %0,%1,%2;" : "=l"(d) : "l"(a), "l"(b)); return d;
}
__device__ __forceinline__ ull pk(float lo, float hi) {
    ull d; asm("mov.b64 %0,{%1,%2};" : "=l"(d) : "f"(lo), "f"(hi)); return d;
}
__device__ __forceinline__ ull sp2(float x) { return pk(x, x); }
__device__ __forceinline__ float flo(ull v) { return __uint_as_float((unsigned)v); }
__device__ __forceinline__ float fhi(ull v) { return __uint_as_float((unsigned)(v >> 32)); }
__device__ __forceinline__ ull lsw(ull v) { return pk(fhi(v), flo(v)); }     // lane swap
__device__ __forceinline__ float tanh_fast(float x) {
    float y; asm("tanh.approx.f32 %0, %1;" : "=f"(y) : "f"(x)); return y;
}
// a - b on the fma pipe (1 op)
__device__ __forceinline__ ull sub2f(ull a, ull b, ull MONE) { return fma2(MONE, b, a); }

// Gate on local wire w in {1..4}: pack-index stride S = 1<<(4-w). Element-wise packed.
template <int S>
__device__ __forceinline__ void gate_local(ull* RE, ull* IM,
                                           float2 G00, float2 G01, float2 G10, float2 G11) {
    ull x00 = sp2(G00.x), ny00 = sp2(-G00.y), y00 = sp2(G00.y);
    ull x01 = sp2(G01.x), ny01 = sp2(-G01.y), y01 = sp2(G01.y);
    ull x10 = sp2(G10.x), ny10 = sp2(-G10.y), y10 = sp2(G10.y);
    ull x11 = sp2(G11.x), ny11 = sp2(-G11.y), y11 = sp2(G11.y);
#pragma unroll
    for (int t = 0; t < 8; t++) {
        int K0 = ((t & ~(S - 1)) << 1) | (t & (S - 1));
        int K1 = K0 + S;
        ull r0 = RE[K0], i0 = IM[K0], r1 = RE[K1], i1 = IM[K1];
        RE[K0] = fma2(x00, r0, fma2(ny00, i0, fma2(x01, r1, mul2(ny01, i1))));
        IM[K0] = fma2(x00, i0, fma2(y00, r0, fma2(x01, i1, mul2(y01, r1))));
        RE[K1] = fma2(x10, r0, fma2(ny10, i0, fma2(x11, r1, mul2(ny11, i1))));
        IM[K1] = fma2(x10, i0, fma2(y10, r0, fma2(x11, i1, mul2(y11, r1))));
    }
}

// Gate on wire 5 (the two lanes inside each pack), swap-form:
// out = P .* st + Q .* laneswap(st), P=(G00,G11), Q=(G01,G10).
__device__ __forceinline__ void gate_w5(ull* RE, ull* IM,
                                        float2 G00, float2 G01, float2 G10, float2 G11) {
    ull Px = pk(G00.x, G11.x), Py = pk(G00.y, G11.y), nPy = pk(-G00.y, -G11.y);
    ull Qx = pk(G01.x, G10.x), Qy = pk(G01.y, G10.y), nQy = pk(-G01.y, -G10.y);
#pragma unroll
    for (int K = 0; K < 16; K++) {
        ull r = RE[K], i = IM[K];
        ull rs = lsw(r), is = lsw(i);
        RE[K] = fma2(Px, r, fma2(nPy, i, fma2(Qx, rs, mul2(nQy, is))));
        IM[K] = fma2(Px, i, fma2(Py, r, fma2(Qx, is, mul2(Qy, rs))));
    }
}

// Wire-5 gate with the ring's cnot(4,5) FOLDED in (odd K gets post-lane-swap,
// realized with lane-swapped coefficient packs — zero extra ops).
__device__ __forceinline__ void gate_w5_foldC45(ull* RE, ull* IM,
                                                float2 G00, float2 G01, float2 G10, float2 G11) {
    {   // even K: normal coefficients
        ull Px = pk(G00.x, G11.x), Py = pk(G00.y, G11.y), nPy = pk(-G00.y, -G11.y);
        ull Qx = pk(G01.x, G10.x), Qy = pk(G01.y, G10.y), nQy = pk(-G01.y, -G10.y);
#pragma unroll
        for (int K = 0; K < 16; K += 2) {
            ull r = RE[K], i = IM[K];
            ull rs = lsw(r), is = lsw(i);
            RE[K] = fma2(Px, r, fma2(nPy, i, fma2(Qx, rs, mul2(nQy, is))));
            IM[K] = fma2(Px, i, fma2(Py, r, fma2(Qx, is, mul2(Qy, rs))));
        }
    }
    {   // odd K: out' = lsw(out) via lane-swapped packs
        ull oPx = pk(G11.x, G00.x), oPy = pk(G11.y, G00.y), onPy = pk(-G11.y, -G00.y);
        ull oQx = pk(G10.x, G01.x), oQy = pk(G10.y, G01.y), onQy = pk(-G10.y, -G01.y);
#pragma unroll
        for (int K = 1; K < 16; K += 2) {
            ull r = RE[K], i = IM[K];
            ull rs = lsw(r), is = lsw(i);
            RE[K] = fma2(oQx, r, fma2(onQy, i, fma2(oPx, rs, mul2(onPy, is))));
            IM[K] = fma2(oQx, i, fma2(oQy, r, fma2(oPx, is, mul2(oPy, rs))));
        }
    }
}

// Gate on wire 0 fused with a PENDING cnot(5,0) from the preceding ring.
// Asymmetric coefficient packs absorb the lane merge; 2-deep SHFL pipeline.
__device__ __forceinline__ void gate_w0_fused(ull* RE, ull* IM, float2 Gd, float2 Go) {
    ull dx = pk(Gd.x, Go.x), ox = pk(Go.x, Gd.x);
    ull dy = pk(Gd.y, Go.y), oy = pk(Go.y, Gd.y);
    ull ndy = pk(-Gd.y, -Go.y), noy = pk(-Go.y, -Gd.y);
    ull pr = __shfl_xor_sync(0xffffffffu, RE[0], 1);
    ull pi = __shfl_xor_sync(0xffffffffu, IM[0], 1);
#pragma unroll
    for (int K = 0; K < 16; K++) {
        ull prn = 0, pin = 0;
        if (K < 15) {
            prn = __shfl_xor_sync(0xffffffffu, RE[K + 1], 1);
            pin = __shfl_xor_sync(0xffffffffu, IM[K + 1], 1);
        }
        ull r = RE[K], i = IM[K];
        RE[K] = fma2(dx, r, fma2(ndy, i, fma2(ox, pr, mul2(noy, pi))));
        IM[K] = fma2(dx, i, fma2(dy, r, fma2(ox, pi, mul2(oy, pr))));
        pr = prn; pi = pin;
    }
}

__device__ __forceinline__ void swp(ull& a, ull& b) { ull t = a; a = b; b = t; }

// Free pack-index renames: cnot(1,2)(2,3)(3,4).
__device__ __forceinline__ void cnot_free_swaps(ull* RE, ull* IM) {
    swp(RE[8], RE[12]); swp(IM[8], IM[12]);
    swp(RE[9], RE[13]); swp(IM[9], IM[13]);
    swp(RE[10], RE[14]); swp(IM[10], IM[14]);
    swp(RE[11], RE[15]); swp(IM[11], IM[15]);
    swp(RE[4], RE[6]);  swp(IM[4], IM[6]);
    swp(RE[5], RE[7]);  swp(IM[5], IM[7]);
    swp(RE[12], RE[14]); swp(IM[12], IM[14]);
    swp(RE[13], RE[15]); swp(IM[13], IM[15]);
    swp(RE[2], RE[3]);  swp(IM[2], IM[3]);
    swp(RE[6], RE[7]);  swp(IM[6], IM[7]);
    swp(RE[10], RE[11]); swp(IM[10], IM[11]);
    swp(RE[14], RE[15]); swp(IM[14], IM[15]);
}

// Ring0 tail: free swaps + explicit cnot(4,5) lane swap on odd packs.
__device__ __forceinline__ void cnot_ring_rest(ull* RE, ull* IM) {
    cnot_free_swaps(RE, IM);
#pragma unroll
    for (int K = 1; K < 16; K += 2) {
        RE[K] = lsw(RE[K]);
        IM[K] = lsw(IM[K]);
    }
}

// Gate coefficient build; M loaded as 2x float4 (16B LDS), sM is 16B-aligned.
__device__ __forceinline__ void makeG(const float2* m, float c, float s,
                                      float2& G00, float2& G01, float2& G10, float2& G11) {
    const float4* m4 = reinterpret_cast<const float4*>(m);
    float4 a = m4[0], bb = m4[1];
    float2 m00 = make_float2(a.x, a.y), m01 = make_float2(a.z, a.w);
    float2 m10 = make_float2(bb.x, bb.y), m11 = make_float2(bb.z, bb.w);
    G00.x = fmaf(c, m00.x, s * m01.x);  G00.y = fmaf(c, m00.y, s * m01.y);
    G01.x = fmaf(-s, m00.x, c * m01.x); G01.y = fmaf(-s, m00.y, c * m01.y);
    G10.x = fmaf(c, m10.x, s * m11.x);  G10.y = fmaf(c, m10.y, s * m11.y);
    G11.x = fmaf(-s, m10.x, c * m11.x); G11.y = fmaf(-s, m10.y, c * m11.y);
}

__global__ __launch_bounds__(128, 4)
void qsim_kernel(const float* __restrict__ x, const float* __restrict__ w,
                 float* __restrict__ out, int B) {
    // In-block gate setup: threads 0..17 build M = RZ(w2)@RY(w1)@RZ(w0).
    __shared__ __align__(16) float2 sM[NL * NQ * 4];
    {
        int g = threadIdx.x;
        if (g < NL * NQ) {
            float w0 = w[g * 3 + 0];
            float w1 = w[g * 3 + 1];
            float w2 = w[g * 3 + 2];
            float s1, c1, sp_, cp_, sm2, cm2;
            sincosf(0.5f * w1, &s1, &c1);
            sincosf(0.5f * (w0 + w2), &sp_, &cp_);
            sincosf(0.5f * (w0 - w2), &sm2, &cm2);
            sM[g * 4 + 0] = make_float2(c1 * cp_, -c1 * sp_);   // M00
            sM[g * 4 + 1] = make_float2(-s1 * cm2, -s1 * sm2);  // M01
            sM[g * 4 + 2] = make_float2(s1 * cm2, -s1 * sm2);   // M10
            sM[g * 4 + 3] = make_float2(c1 * cp_, c1 * sp_);    // M11
        }
    }
    __syncthreads();

    int tid = blockIdx.x * blockDim.x + threadIdx.x;
    int b = tid >> 1;
    if (b >= B) return;
    int p = tid & 1;  // this thread's wire-0 (MSB) value

    // Vectorized x load, then angles.
    float cs[NQ], sn[NQ];
    {
        const float2* xx = reinterpret_cast<const float2*>(x + (size_t)b * NQ);
        float2 x01 = xx[0], x23 = xx[1], x45 = xx[2];
        float xv[NQ] = {x01.x, x01.y, x23.x, x23.y, x45.x, x45.y};
#pragma unroll
        for (int q = 0; q < NQ; q++) {
            float t = 1.5707963267948966f * tanh_fast(xv[q]);
            __sincosf(t, &sn[q], &cs[q]);
        }
    }

    // 32 local amps packed: RE[K] = (re_{2K}, re_{2K+1}), pack lane = wire5.
    // Pack-index bits k3..k0 = wires 1..4.
    ull RE[16], IM[16];

    // ---- Layer 0: product state |0..0> -> tensor of first gate columns.
    //      Ring0's cnot(0,1) folded into the wire-1 factor (v0<->v1 for p=1). ----
    {
        float2 a;  // wire-0 factor for this thread
        {
            float2 ma = p ? sM[2] : sM[0];
            float2 mb = p ? sM[3] : sM[1];
            a.x = fmaf(cs[0], ma.x, sn[0] * mb.x);
            a.y = fmaf(cs[0], ma.y, sn[0] * mb.y);
        }
        {
            float2 m00 = sM[5 * 4 + 0], m01 = sM[5 * 4 + 1];
            float2 m10 = sM[5 * 4 + 2], m11 = sM[5 * 4 + 3];
            float2 v0 = make_float2(fmaf(cs[5], m00.x, sn[5] * m01.x),
                                    fmaf(cs[5], m00.y, sn[5] * m01.y));
            float2 v1 = make_float2(fmaf(cs[5], m10.x, sn[5] * m11.x),
                                    fmaf(cs[5], m10.y, sn[5] * m11.y));
            ull V5X = pk(v0.x, v1.x), V5Y = pk(v0.y, v1.y), V5Yn = pk(-v0.y, -v1.y);
            RE[0] = fma2(sp2(a.x), V5X, mul2(sp2(a.y), V5Yn));
            IM[0] = fma2(sp2(a.x), V5Y, mul2(sp2(a.y), V5X));
        }
#pragma unroll
        for (int q = 1; q <= 4; q++) {
            float2 m00 = sM[q * 4 + 0], m01 = sM[q * 4 + 1];
            float2 m10 = sM[q * 4 + 2], m11 = sM[q * 4 + 3];
            float2 v0 = make_float2(fmaf(cs[q], m00.x, sn[q] * m01.x),
                                    fmaf(cs[q], m00.y, sn[q] * m01.y));
            float2 v1 = make_float2(fmaf(cs[q], m10.x, sn[q] * m11.x),
                                    fmaf(cs[q], m10.y, sn[q] * m11.y));
            if (q == 1) {
                float2 t0 = v0, t1 = v1;
                v0 = p ? t1 : t0;
                v1 = p ? t0 : t1;
            }
            ull x0 = sp2(v0.x), ny0 = sp2(-v0.y), y0 = sp2(v0.y);
            ull x1 = sp2(v1.x), ny1 = sp2(-v1.y), y1 = sp2(v1.y);
            int n = 1 << (q - 1);
#pragma unroll
            for (int k = 15; k >= 0; k--) {
                if (k < n) {
                    ull r = RE[k], i = IM[k];
                    RE[2 * k + 1] = fma2(x1, r, mul2(ny1, i));
                    IM[2 * k + 1] = fma2(x1, i, mul2(y1, r));
                    RE[2 * k]     = fma2(x0, r, mul2(ny0, i));
                    IM[2 * k]     = fma2(x0, i, mul2(y0, r));
                }
            }
        }
    }
    cnot_ring_rest(RE, IM);  // ring0: (1,2)(2,3)(3,4)(4,5); cnot(5,0) pending

    // ---- Layer 1: w0(C50 fused), w2..w4, w1(C01 fold), free swaps, then
    //      w5 with cnot(4,5) FOLDED. Leaves cnot(5,0) pending. ----
    {
        const float2* mbase = &sM[1 * NQ * 4];
        float2 G00, G01, G10, G11;
        {
            float2 ma = p ? mbase[2] : mbase[0];
            float2 mb = p ? mbase[3] : mbase[1];
            float c = cs[0], s = sn[0];
            float2 u = make_float2(fmaf(c, ma.x, s * mb.x), fmaf(c, ma.y, s * mb.y));
            float2 v = make_float2(fmaf(-s, ma.x, c * mb.x), fmaf(-s, ma.y, c * mb.y));
            float2 Gd = p ? v : u;
            float2 Go = p ? u : v;
            gate_w0_fused(RE, IM, Gd, Go);
        }
        makeG(mbase + 8, cs[2], sn[2], G00, G01, G10, G11);
        gate_local<4>(RE, IM, G00, G01, G10, G11);
        makeG(mbase + 12, cs[3], sn[3], G00, G01, G10, G11);
        gate_local<2>(RE, IM, G00, G01, G10, G11);
        makeG(mbase + 16, cs[4], sn[4], G00, G01, G10, G11);
        gate_local<1>(RE, IM, G00, G01, G10, G11);
        makeG(mbase + 4, cs[1], sn[1], G00, G01, G10, G11);
        {
            float2 H00 = p ? G10 : G00, H01 = p ? G11 : G01;
            float2 H10 = p ? G00 : G10, H11 = p ? G01 : G11;
            gate_local<8>(RE, IM, H00, H01, H10, H11);
        }
        cnot_free_swaps(RE, IM);
        makeG(mbase + 20, cs[5], sn[5], G00, G01, G10, G11);
        gate_w5_foldC45(RE, IM, G00, G01, G10, G11);
    }

    // ---- Layer 2 (final): w0(C50 fused), w2..w4, w5. The final wire-1 gate
    //      is FUSED into the readout via unitarity (below); the entire final
    //      CNOT ring is folded into the readout sign permutation. ----
    const float2* mbase2 = &sM[2 * NQ * 4];
    {
        float2 G00, G01, G10, G11;
        {
            float2 ma = p ? mbase2[2] : mbase2[0];
            float2 mb = p ? mbase2[3] : mbase2[1];
            float c = cs[0], s = sn[0];
            float2 u = make_float2(fmaf(c, ma.x, s * mb.x), fmaf(c, ma.y, s * mb.y));
            float2 v = make_float2(fmaf(-s, ma.x, c * mb.x), fmaf(-s, ma.y, c * mb.y));
            float2 Gd = p ? v : u;
            float2 Go = p ? u : v;
            gate_w0_fused(RE, IM, Gd, Go);
        }
        makeG(mbase2 + 8, cs[2], sn[2], G00, G01, G10, G11);
        gate_local<4>(RE, IM, G00, G01, G10, G11);
        makeG(mbase2 + 12, cs[3], sn[3], G00, G01, G10, G11);
        gate_local<2>(RE, IM, G00, G01, G10, G11);
        makeG(mbase2 + 16, cs[4], sn[4], G00, G01, G10, G11);
        gate_local<1>(RE, IM, G00, G01, G10, G11);
        makeG(mbase2 + 20, cs[5], sn[5], G00, G01, G10, G11);
        gate_w5(RE, IM, G00, G01, G10, G11);
        // (no w1 gate — fused into DP below)
    }

    // ---- Readout with final-w1-gate fusion + final-ring fold.
    //   |u|^2-|v|^2 = alpha*(|a|^2-|b|^2)
    //               + 4*[Re(G00 cG01)*Re(a cb) - Im(G00 cG01)*Im(a cb)]
    //   alpha = |G00|^2-|G10|^2. Then 3-level Walsh on DP (wires 2,3,4). ----
    const ull MONE = sp2(-1.0f);
    ull tA, tBr, tBi;
    {
        const float4* m4 = reinterpret_cast<const float4*>(mbase2 + 4);
        float4 ah = m4[0], bh = m4[1];
        float c = cs[1], s = sn[1];
        float2 g00 = make_float2(fmaf(c, ah.x, s * ah.z), fmaf(c, ah.y, s * ah.w));
        float2 g01 = make_float2(fmaf(-s, ah.x, c * ah.z), fmaf(-s, ah.y, c * ah.w));
        float2 g10 = make_float2(fmaf(c, bh.x, s * bh.z), fmaf(c, bh.y, s * bh.w));
        float alpha = fmaf(g00.x, g00.x, g00.y * g00.y)
                    - fmaf(g10.x, g10.x, g10.y * g10.y);
        float betr = 4.0f * fmaf(g00.x, g01.x, g00.y * g01.y);   // 4*Re(G00 cG01)
        float beti = 4.0f * fmaf(g00.x, g01.y, -g00.y * g01.x);  // -4*Im(G00 cG01)
        tA = sp2(alpha); tBr = sp2(betr); tBi = sp2(beti);
    }
    ull DP[8];
#pragma unroll
    for (int K = 0; K < 8; K++) {
        ull ar = RE[K], ai = IM[K], br = RE[K + 8], bi = IM[K + 8];
        ull na = fma2(ar, ar, mul2(ai, ai));                    // |a|^2
        ull nb = fma2(br, br, mul2(bi, bi));                    // |b|^2
        ull Z  = sub2f(na, nb, MONE);
        ull Rc = fma2(ai, bi, mul2(ar, br));                    // Re(a conj b)
        ull Ic = sub2f(mul2(ai, br), mul2(ar, bi), MONE);       // Im(a conj b)
        DP[K] = fma2(tA, Z, fma2(tBr, Rc, mul2(tBi, Ic)));
    }
    // Walsh butterfly on DP: bit0 first, then bit1, then bit2.
    ull A0 = add2(DP[0], DP[1]), A1 = add2(DP[2], DP[3]);
    ull A2 = add2(DP[4], DP[5]), A3 = add2(DP[6], DP[7]);
    ull D0 = sub2f(DP[0], DP[1], MONE), D1 = sub2f(DP[2], DP[3], MONE);
    ull D2 = sub2f(DP[4], DP[5], MONE), D3 = sub2f(DP[6], DP[7], MONE);
    ull S0 = add2(A0, A1), S1 = add2(A2, A3);
    ull U0 = sub2f(A0, A1, MONE), U1 = sub2f(A2, A3, MONE);
    ull V0 = sub2f(D0, D1, MONE), V1 = sub2f(D2, D3, MONE);
    ull E1v = add2(S0, S1);            // sign: wire1 only (in DP)
    ull E2v = sub2f(S0, S1, MONE);     // + wire2
    ull E3v = sub2f(U0, U1, MONE);     // + wires2,3
    ull E4v = sub2f(V0, V1, MONE);     // + wires2,3,4

    float sg = p ? -1.0f : 1.0f;
    float e1 = sg * (flo(E1v) + fhi(E1v));
    float e2 = sg * (flo(E2v) + fhi(E2v));
    float e3 = sg * (flo(E3v) + fhi(E3v));
    float e4 = sg * (flo(E4v) + fhi(E4v));
    float g5 = flo(E4v) - fhi(E4v);
    float e5 = sg * g5;
    float e0 = g5;

    e0 += __shfl_xor_sync(0xffffffffu, e0, 1);
    e1 += __shfl_xor_sync(0xffffffffu, e1, 1);
    e2 += __shfl_xor_sync(0xffffffffu, e2, 1);
    e3 += __shfl_xor_sync(0xffffffffu, e3, 1);
    e4 += __shfl_xor_sync(0xffffffffu, e4, 1);
    e5 += __shfl_xor_sync(0xffffffffu, e5, 1);

    float* ob = out + (size_t)b * NQ;
    if (p == 0) {
        *reinterpret_cast<float2*>(ob) = make_float2(e0, e1);
        ob[2] = e2;
    } else {
        ob[3] = e3;
        *reinterpret_cast<float2*>(ob + 4) = make_float2(e4, e5);
    }
}

extern "C" void kernel_launch(void* const* d_in, const int* in_sizes, int n_in,
                              void* d_out, int out_size) {
    const float* x = (const float*)d_in[0];
    const float* w = (const float*)d_in[1];
    float* out = (float*)d_out;
    int B = in_sizes[0] / NQ;

    const int threads = 128;
    long long total = 2LL * B;
    int blocks = (int)((total + threads - 1) / threads);
    qsim_kernel<<<blocks, threads>>>(x, w, out, B);
}